// round 14
// baseline (speedup 1.0000x reference)
#include <cuda_runtime.h>
#include <cuda_bf16.h>
#include <math.h>
#include <stdint.h>

#define BATCH 4
#define SEQ   1024
#define DM    768
#define NH    12
#define HD    64
#define FF    3072
#define NL    6
#define MTOT  (BATCH*SEQ)        // 4096
#define QKVD  (3*DM)             // 2304

typedef unsigned long long u64;
typedef __nv_bfloat16 bf16;

// ---------------- scratch (no cudaMalloc allowed) ----------------
__device__ float g_h  [MTOT*DM];
__device__ float g_mid[MTOT*DM];
__device__ bf16  g_hh [MTOT*DM],  g_hl [MTOT*DM];
__device__ bf16  g_qh [MTOT*QKVD], g_ql [MTOT*QKVD];
__device__ bf16  g_ch [MTOT*DM],  g_cl [MTOT*DM];
__device__ bf16  g_mh [MTOT*FF],  g_ml [MTOT*FF];
__device__ bf16  g_wqkvT_h[NL*QKVD*DM], g_wqkvT_l[NL*QKVD*DM];
__device__ bf16  g_woT_h  [NL*DM*DM],   g_woT_l  [NL*DM*DM];
__device__ bf16  g_w1T_h  [NL*FF*DM],   g_w1T_l  [NL*FF*DM];
__device__ bf16  g_w2T_h  [NL*DM*FF],   g_w2T_l  [NL*DM*FF];

// ---------------- helpers ----------------
__device__ __forceinline__ uint32_t smem_u32(const void* p) {
    uint32_t a;
    asm("{ .reg .u64 t; cvta.to.shared.u64 t, %1; cvt.u32.u64 %0, t; }" : "=r"(a) : "l"(p));
    return a;
}
__device__ __forceinline__ void cpasync16(uint32_t s, const void* g) {
    asm volatile("cp.async.cg.shared.global [%0], [%1], 16;" :: "r"(s), "l"(g));
}
#define CP_COMMIT() asm volatile("cp.async.commit_group;" ::: "memory")
#define CP_WAIT0()  asm volatile("cp.async.wait_group 0;" ::: "memory")

__device__ __forceinline__ void ldmx4(uint32_t* r, uint32_t a) {
    asm volatile("ldmatrix.sync.aligned.m8n8.x4.shared.b16 {%0,%1,%2,%3}, [%4];"
        : "=r"(r[0]), "=r"(r[1]), "=r"(r[2]), "=r"(r[3]) : "r"(a));
}
__device__ __forceinline__ void ldmx2(uint32_t* r, uint32_t a) {
    asm volatile("ldmatrix.sync.aligned.m8n8.x2.shared.b16 {%0,%1}, [%2];"
        : "=r"(r[0]), "=r"(r[1]) : "r"(a));
}
__device__ __forceinline__ void mma16816(float* c, const uint32_t* a, const uint32_t* b) {
    asm volatile("mma.sync.aligned.m16n8k16.row.col.f32.bf16.bf16.f32 "
        "{%0,%1,%2,%3}, {%4,%5,%6,%7}, {%8,%9}, {%0,%1,%2,%3};"
        : "+f"(c[0]), "+f"(c[1]), "+f"(c[2]), "+f"(c[3])
        : "r"(a[0]), "r"(a[1]), "r"(a[2]), "r"(a[3]), "r"(b[0]), "r"(b[1]));
}

__device__ __forceinline__ u64 ffma2(u64 a, u64 b, u64 c) {
    u64 d; asm("fma.rn.f32x2 %0,%1,%2,%3;" : "=l"(d) : "l"(a), "l"(b), "l"(c)); return d;
}
__device__ __forceinline__ u64 pack_dup(float x) {
    u64 d; asm("mov.b64 %0,{%1,%1};" : "=l"(d) : "r"(__float_as_uint(x))); return d;
}
__device__ __forceinline__ float lo32(u64 v) { return __uint_as_float((unsigned)(v & 0xffffffffull)); }
__device__ __forceinline__ float hi32(u64 v) { return __uint_as_float((unsigned)(v >> 32)); }

__device__ __forceinline__ void split2(float c0, float c1, bf16* ph, bf16* pl) {
    bf16 h0 = __float2bfloat16(c0), h1 = __float2bfloat16(c1);
    __nv_bfloat162 vh; vh.x = h0; vh.y = h1;
    __nv_bfloat162 vl;
    vl.x = __float2bfloat16(c0 - __bfloat162float(h0));
    vl.y = __float2bfloat16(c1 - __bfloat162float(h1));
    *(__nv_bfloat162*)ph = vh;
    *(__nv_bfloat162*)pl = vl;
}

// ---------------- weight transpose-split (vectorized; z = layer) ----------------
// tile row padded to 36 floats (144 B) so float4 fills are 16B-aligned.
__global__ __launch_bounds__(256)
void wsplit_kernel(const float* __restrict__ W, bf16* __restrict__ Th,
                   bf16* __restrict__ Tl, int K, int N) {
    __shared__ float tile[32][36];
    size_t loff = (size_t)blockIdx.z * K * N;
    int nb = blockIdx.x * 32, kb = blockIdx.y * 32;
    int t = threadIdx.x;
    {
        int r = t >> 3, c4 = (t & 7) * 4;     // 32 rows x 8 float4
        *(float4*)&tile[r][c4] =
            *(const float4*)(W + loff + (size_t)(kb + r) * N + nb + c4);
    }
    __syncthreads();
    {
        int wid = t >> 5, lane = t & 31;
        int col = wid*4 + (lane >> 3);        // n - nb, 0..31
        int k4  = (lane & 7) * 4;             // k - kb, step 4
        float v0 = tile[k4+0][col];
        float v1 = tile[k4+1][col];
        float v2 = tile[k4+2][col];
        float v3 = tile[k4+3][col];
        bf16 h0 = __float2bfloat16(v0), h1 = __float2bfloat16(v1);
        bf16 h2 = __float2bfloat16(v2), h3 = __float2bfloat16(v3);
        __nv_bfloat162 ph0; ph0.x = h0; ph0.y = h1;
        __nv_bfloat162 ph1; ph1.x = h2; ph1.y = h3;
        __nv_bfloat162 pl0, pl1;
        pl0.x = __float2bfloat16(v0 - __bfloat162float(h0));
        pl0.y = __float2bfloat16(v1 - __bfloat162float(h1));
        pl1.x = __float2bfloat16(v2 - __bfloat162float(h2));
        pl1.y = __float2bfloat16(v3 - __bfloat162float(h3));
        size_t o = loff + (size_t)(nb + col) * K + kb + k4;
        *(__nv_bfloat162*)(Th + o)     = ph0;
        *(__nv_bfloat162*)(Th + o + 2) = ph1;
        *(__nv_bfloat162*)(Tl + o)     = pl0;
        *(__nv_bfloat162*)(Tl + o + 2) = pl1;
    }
}

// ---------------- mma.sync bf16-split GEMM + fused epilogue split ----------------
#define ROWB  80
#define TILEB (128*ROWB)
#define GEMM_SMEM (8*TILEB)
__global__ __launch_bounds__(256, 2)
void gemm_bf16_kernel(const bf16* __restrict__ Ah, const bf16* __restrict__ Al,
                      const bf16* __restrict__ Bh, const bf16* __restrict__ Bl,
                      const float* __restrict__ bias,
                      float* __restrict__ Cf, bf16* __restrict__ Ch, bf16* __restrict__ Cl,
                      int M, int N, int K, int relu)
{
    extern __shared__ char smem[];
    const uint32_t sb = smem_u32(smem);
    const int tid = threadIdx.x, lane = tid & 31, wid = tid >> 5;
    const int wm = (wid & 1) * 64, wn = (wid >> 1) * 32;
    const int m0 = blockIdx.y * 128, n0 = blockIdx.x * 128;

    const bf16* gsrc[4] = { Ah + (size_t)m0*K, Al + (size_t)m0*K,
                            Bh + (size_t)n0*K, Bl + (size_t)n0*K };

    const int lrow = tid >> 1;
    const int lc0  = (tid & 1) * 2;

    const int aMoff = ((lane >> 3) & 1) * 8 + (lane & 7);
    const int aKby  = (lane >> 4) * 16;
    const int bNoff4 = (lane >> 4) * 8 + (lane & 7);
    const int bKby4  = ((lane >> 3) & 1) * 16;

    const int nchunk = K >> 5;

    {
        uint32_t dst = sb;
#pragma unroll
        for (int v = 0; v < 4; v++) {
            const bf16* g = gsrc[v] + (size_t)lrow*K + lc0*8;
            uint32_t s = dst + v*TILEB + lrow*ROWB + lc0*16;
            cpasync16(s, g);
            cpasync16(s + 16, g + 8);
        }
        CP_COMMIT();
    }

    float acc[4][4][4];
#pragma unroll
    for (int a = 0; a < 4; a++)
#pragma unroll
        for (int b = 0; b < 4; b++)
#pragma unroll
            for (int c = 0; c < 4; c++) acc[a][b][c] = 0.f;

    for (int t = 0; t < nchunk; t++) {
        CP_WAIT0();
        __syncthreads();
        if (t + 1 < nchunk) {
            int k0 = (t + 1) * 32;
            uint32_t dst = sb + ((t + 1) & 1) * 4*TILEB;
#pragma unroll
            for (int v = 0; v < 4; v++) {
                const bf16* g = gsrc[v] + (size_t)lrow*K + k0 + lc0*8;
                uint32_t s = dst + v*TILEB + lrow*ROWB + lc0*16;
                cpasync16(s, g);
                cpasync16(s + 16, g + 8);
            }
            CP_COMMIT();
        }

        uint32_t base = sb + (t & 1) * 4*TILEB;
#pragma unroll
        for (int kk = 0; kk < 2; kk++) {
            uint32_t bh[4][2], bl[4][2];
#pragma unroll
            for (int np = 0; np < 2; np++) {
                uint32_t baddr = base + 2*TILEB + (wn + np*16 + bNoff4)*ROWB + kk*32 + bKby4;
                uint32_t r4[4];
                ldmx4(r4, baddr);
                bh[np*2][0] = r4[0]; bh[np*2][1] = r4[1];
                bh[np*2+1][0] = r4[2]; bh[np*2+1][1] = r4[3];
                ldmx4(r4, baddr + TILEB);
                bl[np*2][0] = r4[0]; bl[np*2][1] = r4[1];
                bl[np*2+1][0] = r4[2]; bl[np*2+1][1] = r4[3];
            }
#pragma unroll
            for (int mt = 0; mt < 4; mt++) {
                uint32_t ah[4], al[4];
                uint32_t aaddr = base + (wm + mt*16 + aMoff)*ROWB + kk*32 + aKby;
                ldmx4(ah, aaddr);
                ldmx4(al, aaddr + TILEB);
#pragma unroll
                for (int nt = 0; nt < 4; nt++) {
                    mma16816(acc[mt][nt], ah, bh[nt]);
                    mma16816(acc[mt][nt], al, bh[nt]);
                    mma16816(acc[mt][nt], ah, bl[nt]);
                }
            }
        }
    }

    const int r0 = lane >> 2, cq = (lane & 3) * 2;
#pragma unroll
    for (int mt = 0; mt < 4; mt++) {
#pragma unroll
        for (int nt = 0; nt < 4; nt++) {
            int row = m0 + wm + mt*16 + r0;
            int col = n0 + wn + nt*8 + cq;
            float b0 = bias[col], b1 = bias[col + 1];
            float c0 = acc[mt][nt][0] + b0, c1 = acc[mt][nt][1] + b1;
            float c2 = acc[mt][nt][2] + b0, c3 = acc[mt][nt][3] + b1;
            if (relu) {
                c0 = fmaxf(c0, 0.f); c1 = fmaxf(c1, 0.f);
                c2 = fmaxf(c2, 0.f); c3 = fmaxf(c3, 0.f);
            }
            size_t o0 = (size_t)row*N + col, o1 = (size_t)(row + 8)*N + col;
            if (Cf) {
                *(float2*)&Cf[o0] = make_float2(c0, c1);
                *(float2*)&Cf[o1] = make_float2(c2, c3);
            }
            if (Ch) {
                split2(c0, c1, Ch + o0, Cl + o0);
                split2(c2, c3, Ch + o1, Cl + o1);
            }
        }
    }
}

// ---------------- positional encoding add (+ split) ----------------
__global__ void pos_add_kernel(const float* __restrict__ x, float* __restrict__ out,
                               bf16* __restrict__ oh, bf16* __restrict__ ol) {
    int row = blockIdx.x;
    int s = row & (SEQ - 1);
    const float c = -logf(10000.0f) / (float)DM;
    for (int d = threadIdx.x; d < DM; d += blockDim.x) {
        int i2 = d & ~1;
        float ang = (float)s * expf((float)i2 * c);
        float pe = (d & 1) ? cosf(ang) : sinf(ang);
        float v = x[(size_t)row*DM + d] + pe;
        out[(size_t)row*DM + d] = v;
        bf16 hv = __float2bfloat16(v);
        oh[(size_t)row*DM + d] = hv;
        ol[(size_t)row*DM + d] = __float2bfloat16(v - __bfloat162float(hv));
    }
}

// ---------------- attention: TC scores + SIMT softmax/PV; V from splits ----------
#define P_LD   1032
#define QPITCH 72                 // bf16 per Q/K smem row (144 B)
#define SM_P   0
#define SM_QH  (32*P_LD*4)                       // 132096
#define SM_QL  (SM_QH + 32*QPITCH*2)
#define SM_KH  (SM_QL + 32*QPITCH*2)
#define SM_KL  (SM_KH + 128*QPITCH*2)
#define SM_V   SM_KH                              // V fp32 overlays K region
#define ATT_SMEM (SM_KL + 128*QPITCH*2)          // 178176 B
__global__ __launch_bounds__(256)
void attn_kernel(const bf16* __restrict__ qkh, const bf16* __restrict__ qkl,
                 bf16* __restrict__ ctxh, bf16* __restrict__ ctxl)
{
    extern __shared__ char smraw[];
    float* P = (float*)(smraw + SM_P);
    const uint32_t sb = smem_u32(smraw);

    const int tid = threadIdx.x, lane = tid & 31, wid = tid >> 5;
    const int q0  = blockIdx.x * 32;
    const int h   = blockIdx.y;
    const int b   = blockIdx.z;
    const size_t rowbase = (size_t)b*SEQ;
    const int    colQ = h*HD, colK = DM + h*HD, colV = 2*DM + h*HD;

    // ---- load Q tile (hi/lo) ----
    {
        int r = tid >> 3, v = tid & 7;
        *(uint4*)(smraw + SM_QH + (r*QPITCH + v*8)*2) =
            *(const uint4*)(qkh + (rowbase + q0 + r)*QKVD + colQ + v*8);
        *(uint4*)(smraw + SM_QL + (r*QPITCH + v*8)*2) =
            *(const uint4*)(qkl + (rowbase + q0 + r)*QKVD + colQ + v*8);
    }

    const int aMoff = ((lane >> 3) & 1) * 8 + (lane & 7);
    const int aKby  = (lane >> 4) * 16;
    const int bNoff = lane & 7;
    const int bKby  = ((lane >> 3) & 1) * 16;
    const int nbase = wid * 16;
    const float scale = 0.125f;

    for (int kt = 0; kt < 8; kt++) {
#pragma unroll
        for (int i = 0; i < 4; i++) {
            int idx = tid + i*256;
            int r = idx >> 3, v = idx & 7;
            *(uint4*)(smraw + SM_KH + (r*QPITCH + v*8)*2) =
                *(const uint4*)(qkh + (rowbase + kt*128 + r)*QKVD + colK + v*8);
            *(uint4*)(smraw + SM_KL + (r*QPITCH + v*8)*2) =
                *(const uint4*)(qkl + (rowbase + kt*128 + r)*QKVD + colK + v*8);
        }
        __syncthreads();

        float acc[2][2][4];
#pragma unroll
        for (int i = 0; i < 2; i++)
#pragma unroll
            for (int j = 0; j < 2; j++)
#pragma unroll
                for (int c = 0; c < 4; c++) acc[i][j][c] = 0.f;

#pragma unroll
        for (int kk = 0; kk < 4; kk++) {
            uint32_t ah[2][4], al[2][4], bh[2][2], bl[2][2];
#pragma unroll
            for (int mt = 0; mt < 2; mt++) {
                uint32_t aaddr = sb + SM_QH + (mt*16 + aMoff)*QPITCH*2 + kk*32 + aKby;
                ldmx4(ah[mt], aaddr);
                ldmx4(al[mt], aaddr + (SM_QL - SM_QH));
            }
#pragma unroll
            for (int nt = 0; nt < 2; nt++) {
                uint32_t baddr = sb + SM_KH + (nbase + nt*8 + bNoff)*QPITCH*2 + kk*32 + bKby;
                ldmx2(bh[nt], baddr);
                ldmx2(bl[nt], baddr + (SM_KL - SM_KH));
            }
#pragma unroll
            for (int mt = 0; mt < 2; mt++)
#pragma unroll
                for (int nt = 0; nt < 2; nt++) {
                    mma16816(acc[mt][nt], ah[mt], bh[nt]);
                    mma16816(acc[mt][nt], al[mt], bh[nt]);
                    mma16816(acc[mt][nt], ah[mt], bl[nt]);
                }
        }
        const int r0 = lane >> 2, cq = (lane & 3) * 2;
#pragma unroll
        for (int mt = 0; mt < 2; mt++)
#pragma unroll
            for (int nt = 0; nt < 2; nt++) {
                int row = mt*16 + r0;
                int col = kt*128 + nbase + nt*8 + cq;
                P[row*P_LD + col]       = acc[mt][nt][0] * scale;
                P[row*P_LD + col + 1]   = acc[mt][nt][1] * scale;
                P[(row+8)*P_LD + col]   = acc[mt][nt][2] * scale;
                P[(row+8)*P_LD + col+1] = acc[mt][nt][3] * scale;
            }
        __syncthreads();
    }

    // ---- softmax + clip per row (warp per row) ----
    for (int r = wid; r < 32; r += 8) {
        float* row = P + r*P_LD;
        float m = -INFINITY;
        for (int t = lane; t < 1024; t += 32) m = fmaxf(m, row[t]);
#pragma unroll
        for (int o = 16; o; o >>= 1) m = fmaxf(m, __shfl_xor_sync(~0u, m, o));
        float s = 0.f;
        for (int t = lane; t < 1024; t += 32) { float e = __expf(row[t] - m); row[t] = e; s += e; }
#pragma unroll
        for (int o = 16; o; o >>= 1) s += __shfl_xor_sync(~0u, s, o);
        float inv = 1.f / s;
        for (int t = lane; t < 1024; t += 32)
            row[t] = fminf(fmaxf(row[t]*inv, 1e-6f), 1.f);
    }
    __syncthreads();

    // ---- O = P @ V : SIMT f32x2, V reconstructed from bf16 splits ----
    float* Vs = (float*)(smraw + SM_V);
    const int txo = tid & 15;
    const int tyo = tid >> 4;
    u64 oacc[2][2] = { {0ull,0ull}, {0ull,0ull} };
    for (int vt = 0; vt < 8; vt++) {
        for (int f = tid; f < 128*8; f += 256) {
            int r = f >> 3, v = f & 7;
            uint4 hv = *(const uint4*)(qkh + (rowbase + vt*128 + r)*QKVD + colV + v*8);
            uint4 lv = *(const uint4*)(qkl + (rowbase + vt*128 + r)*QKVD + colV + v*8);
            const __nv_bfloat162* hp = (const __nv_bfloat162*)&hv;
            const __nv_bfloat162* lp = (const __nv_bfloat162*)&lv;
            float4 o0, o1;
            float2 a, bb;
            a = __bfloat1622float2(hp[0]); bb = __bfloat1622float2(lp[0]);
            o0.x = a.x + bb.x; o0.y = a.y + bb.y;
            a = __bfloat1622float2(hp[1]); bb = __bfloat1622float2(lp[1]);
            o0.z = a.x + bb.x; o0.w = a.y + bb.y;
            a = __bfloat1622float2(hp[2]); bb = __bfloat1622float2(lp[2]);
            o1.x = a.x + bb.x; o1.y = a.y + bb.y;
            a = __bfloat1622float2(hp[3]); bb = __bfloat1622float2(lp[3]);
            o1.z = a.x + bb.x; o1.w = a.y + bb.y;
            *(float4*)&Vs[r*64 + v*8]     = o0;
            *(float4*)&Vs[r*64 + v*8 + 4] = o1;
        }
        __syncthreads();
#pragma unroll 4
        for (int k = 0; k < 128; k++) {
            u64 p0 = pack_dup(P[(tyo*2 + 0)*P_LD + vt*128 + k]);
            u64 p1 = pack_dup(P[(tyo*2 + 1)*P_LD + vt*128 + k]);
#pragma unroll
            for (int j = 0; j < 2; j++) {
                u64 v = *(const u64*)&Vs[k*64 + 2*(txo + 16*j)];
                oacc[0][j] = ffma2(p0, v, oacc[0][j]);
                oacc[1][j] = ffma2(p1, v, oacc[1][j]);
            }
        }
        __syncthreads();
    }
#pragma unroll
    for (int i = 0; i < 2; i++)
#pragma unroll
        for (int j = 0; j < 2; j++) {
            size_t o = (rowbase + q0 + tyo*2 + i)*DM + h*HD + 2*(txo + 16*j);
            split2(lo32(oacc[i][j]), hi32(oacc[i][j]), ctxh + o, ctxl + o);
        }
}

// ---------------- LayerNorm (+ optional split out) ----------------
__global__ __launch_bounds__(256)
void ln_kernel(const float* __restrict__ base, const float* __restrict__ delta,
               const float* __restrict__ g, const float* __restrict__ bta,
               float* __restrict__ out, bf16* __restrict__ oh, bf16* __restrict__ ol)
{
    __shared__ float rowv[DM];
    __shared__ float red[256];
    int row = blockIdx.x, tid = threadIdx.x;
    float local = 0.f;
    for (int d = tid; d < DM; d += 256) {
        float v = base[(size_t)row*DM + d];
        if (delta) v += delta[(size_t)row*DM + d];
        rowv[d] = v; local += v;
    }
    red[tid] = local; __syncthreads();
#pragma unroll
    for (int o = 128; o; o >>= 1) { if (tid < o) red[tid] += red[tid + o]; __syncthreads(); }
    float mean = red[0] * (1.0f/DM);
    __syncthreads();
    local = 0.f;
    for (int d = tid; d < DM; d += 256) { float dv = rowv[d] - mean; local += dv*dv; }
    red[tid] = local; __syncthreads();
#pragma unroll
    for (int o = 128; o; o >>= 1) { if (tid < o) red[tid] += red[tid + o]; __syncthreads(); }
    float inv = rsqrtf(red[0] * (1.0f/DM) + 1e-5f);
    for (int d = tid; d < DM; d += 256) {
        float v = (rowv[d] - mean)*inv*g[d] + bta[d];
        out[(size_t)row*DM + d] = v;
        if (oh) {
            bf16 hv = __float2bfloat16(v);
            oh[(size_t)row*DM + d] = hv;
            ol[(size_t)row*DM + d] = __float2bfloat16(v - __bfloat162float(hv));
        }
    }
}

// ---------------- orchestration ----------------
extern "C" void kernel_launch(void* const* d_in, const int* in_sizes, int n_in,
                              void* d_out, int out_size)
{
    const float* x    = (const float*)d_in[0];
    const float* Wqkv = (const float*)d_in[1];
    const float* bqkv = (const float*)d_in[2];
    const float* Wo   = (const float*)d_in[3];
    const float* bo   = (const float*)d_in[4];
    const float* ln1g = (const float*)d_in[5];
    const float* ln1b = (const float*)d_in[6];
    const float* W1   = (const float*)d_in[7];
    const float* b1   = (const float*)d_in[8];
    const float* W2   = (const float*)d_in[9];
    const float* b2   = (const float*)d_in[10];
    const float* ln2g = (const float*)d_in[11];
    const float* ln2b = (const float*)d_in[12];
    const float* lnfg = (const float*)d_in[13];
    const float* lnfb = (const float*)d_in[14];
    float* out = (float*)d_out;

    float *h, *mid;
    bf16 *hh, *hl, *qh, *ql, *ch, *cl, *mh, *ml;
    bf16 *wqkvTh, *wqkvTl, *woTh, *woTl, *w1Th, *w1Tl, *w2Th, *w2Tl;
    cudaGetSymbolAddress((void**)&h,   g_h);
    cudaGetSymbolAddress((void**)&mid, g_mid);
    cudaGetSymbolAddress((void**)&hh,  g_hh);
    cudaGetSymbolAddress((void**)&hl,  g_hl);
    cudaGetSymbolAddress((void**)&qh,  g_qh);
    cudaGetSymbolAddress((void**)&ql,  g_ql);
    cudaGetSymbolAddress((void**)&ch,  g_ch);
    cudaGetSymbolAddress((void**)&cl,  g_cl);
    cudaGetSymbolAddress((void**)&mh,  g_mh);
    cudaGetSymbolAddress((void**)&ml,  g_ml);
    cudaGetSymbolAddress((void**)&wqkvTh, g_wqkvT_h);
    cudaGetSymbolAddress((void**)&wqkvTl, g_wqkvT_l);
    cudaGetSymbolAddress((void**)&woTh, g_woT_h);
    cudaGetSymbolAddress((void**)&woTl, g_woT_l);
    cudaGetSymbolAddress((void**)&w1Th, g_w1T_h);
    cudaGetSymbolAddress((void**)&w1Tl, g_w1T_l);
    cudaGetSymbolAddress((void**)&w2Th, g_w2T_h);
    cudaGetSymbolAddress((void**)&w2Tl, g_w2T_l);

    cudaFuncSetAttribute(attn_kernel, cudaFuncAttributeMaxDynamicSharedMemorySize,
                         (int)ATT_SMEM);
    cudaFuncSetAttribute(gemm_bf16_kernel, cudaFuncAttributeMaxDynamicSharedMemorySize,
                         GEMM_SMEM);

    // weight transpose+split: one launch per weight type, z = layer
    wsplit_kernel<<<dim3(QKVD/32, DM/32, NL), 256>>>(Wqkv, wqkvTh, wqkvTl, DM, QKVD);
    wsplit_kernel<<<dim3(DM/32,   DM/32, NL), 256>>>(Wo,   woTh,   woTl,   DM, DM);
    wsplit_kernel<<<dim3(FF/32,   DM/32, NL), 256>>>(W1,   w1Th,   w1Tl,   DM, FF);
    wsplit_kernel<<<dim3(DM/32,   FF/32, NL), 256>>>(W2,   w2Th,   w2Tl,   FF, DM);

    pos_add_kernel<<<MTOT, 256>>>(x, h, hh, hl);

    for (int l = 0; l < NL; l++) {
        // qkv = h @ Wqkv + bqkv  (splits only; V reconstructed from splits in attn)
        gemm_bf16_kernel<<<dim3(QKVD/128, MTOT/128), 256, GEMM_SMEM>>>(
            hh, hl, wqkvTh + (size_t)l*QKVD*DM, wqkvTl + (size_t)l*QKVD*DM,
            bqkv + (size_t)l*QKVD, nullptr, qh, ql, MTOT, QKVD, DM, 0);
        // attention -> ctx splits
        attn_kernel<<<dim3(SEQ/32, NH, BATCH), 256, ATT_SMEM>>>(qh, ql, ch, cl);
        // proj = ctx @ Wo + bo (f32 only)
        gemm_bf16_kernel<<<dim3(DM/128, MTOT/128), 256, GEMM_SMEM>>>(
            ch, cl, woTh + (size_t)l*DM*DM, woTl + (size_t)l*DM*DM,
            bo + (size_t)l*DM, mid, nullptr, nullptr, MTOT, DM, DM, 0);
        ln_kernel<<<MTOT, 256>>>(h, mid, ln1g + (size_t)l*DM, ln1b + (size_t)l*DM, h, hh, hl);
        // mid = relu(h @ W1 + b1)  (splits only)
        gemm_bf16_kernel<<<dim3(FF/128, MTOT/128), 256, GEMM_SMEM>>>(
            hh, hl, w1Th + (size_t)l*FF*DM, w1Tl + (size_t)l*FF*DM,
            b1 + (size_t)l*FF, nullptr, mh, ml, MTOT, FF, DM, 1);
        // ffn = mid @ W2 + b2 (f32 only)
        gemm_bf16_kernel<<<dim3(DM/128, MTOT/128), 256, GEMM_SMEM>>>(
            mh, ml, w2Th + (size_t)l*DM*FF, w2Tl + (size_t)l*DM*FF,
            b2 + (size_t)l*DM, mid, nullptr, nullptr, MTOT, DM, FF, 0);
        ln_kernel<<<MTOT, 256>>>(h, mid, ln2g + (size_t)l*DM, ln2b + (size_t)l*DM, h, hh, hl);
    }

    ln_kernel<<<MTOT, 256>>>(h, nullptr, lnfg, lnfb, out, nullptr, nullptr);
}

// round 16
// speedup vs baseline: 1.0302x; 1.0302x over previous
#include <cuda_runtime.h>
#include <cuda_bf16.h>
#include <math.h>
#include <stdint.h>

#define BATCH 4
#define SEQ   1024
#define DM    768
#define NH    12
#define HD    64
#define FF    3072
#define NL    6
#define MTOT  (BATCH*SEQ)        // 4096
#define QKVD  (3*DM)             // 2304

typedef unsigned long long u64;
typedef __nv_bfloat16 bf16;

// ---------------- scratch (no cudaMalloc allowed) ----------------
__device__ float g_h  [MTOT*DM];
__device__ float g_qkv[MTOT*QKVD];     // only V third written/used
__device__ float g_mid[MTOT*DM];
__device__ bf16  g_hh [MTOT*DM],  g_hl [MTOT*DM];
__device__ bf16  g_qh [MTOT*QKVD], g_ql [MTOT*QKVD];
__device__ bf16  g_ch [MTOT*DM],  g_cl [MTOT*DM];
__device__ bf16  g_mh [MTOT*FF],  g_ml [MTOT*FF];
__device__ bf16  g_wqkvT_h[NL*QKVD*DM], g_wqkvT_l[NL*QKVD*DM];
__device__ bf16  g_woT_h  [NL*DM*DM],   g_woT_l  [NL*DM*DM];
__device__ bf16  g_w1T_h  [NL*FF*DM],   g_w1T_l  [NL*FF*DM];
__device__ bf16  g_w2T_h  [NL*DM*FF],   g_w2T_l  [NL*DM*FF];

// ---------------- helpers ----------------
__device__ __forceinline__ uint32_t smem_u32(const void* p) {
    uint32_t a;
    asm("{ .reg .u64 t; cvta.to.shared.u64 t, %1; cvt.u32.u64 %0, t; }" : "=r"(a) : "l"(p));
    return a;
}
__device__ __forceinline__ void cpasync16(uint32_t s, const void* g) {
    asm volatile("cp.async.cg.shared.global [%0], [%1], 16;" :: "r"(s), "l"(g));
}
#define CP_COMMIT() asm volatile("cp.async.commit_group;" ::: "memory")
#define CP_WAIT0()  asm volatile("cp.async.wait_group 0;" ::: "memory")

__device__ __forceinline__ void ldmx4(uint32_t* r, uint32_t a) {
    asm volatile("ldmatrix.sync.aligned.m8n8.x4.shared.b16 {%0,%1,%2,%3}, [%4];"
        : "=r"(r[0]), "=r"(r[1]), "=r"(r[2]), "=r"(r[3]) : "r"(a));
}
__device__ __forceinline__ void ldmx2(uint32_t* r, uint32_t a) {
    asm volatile("ldmatrix.sync.aligned.m8n8.x2.shared.b16 {%0,%1}, [%2];"
        : "=r"(r[0]), "=r"(r[1]) : "r"(a));
}
__device__ __forceinline__ void mma16816(float* c, const uint32_t* a, const uint32_t* b) {
    asm volatile("mma.sync.aligned.m16n8k16.row.col.f32.bf16.bf16.f32 "
        "{%0,%1,%2,%3}, {%4,%5,%6,%7}, {%8,%9}, {%0,%1,%2,%3};"
        : "+f"(c[0]), "+f"(c[1]), "+f"(c[2]), "+f"(c[3])
        : "r"(a[0]), "r"(a[1]), "r"(a[2]), "r"(a[3]), "r"(b[0]), "r"(b[1]));
}

__device__ __forceinline__ u64 ffma2(u64 a, u64 b, u64 c) {
    u64 d; asm("fma.rn.f32x2 %0,%1,%2,%3;" : "=l"(d) : "l"(a), "l"(b), "l"(c)); return d;
}
__device__ __forceinline__ u64 pack_dup(float x) {
    u64 d; asm("mov.b64 %0,{%1,%1};" : "=l"(d) : "r"(__float_as_uint(x))); return d;
}
__device__ __forceinline__ float lo32(u64 v) { return __uint_as_float((unsigned)(v & 0xffffffffull)); }
__device__ __forceinline__ float hi32(u64 v) { return __uint_as_float((unsigned)(v >> 32)); }

__device__ __forceinline__ void split2(float c0, float c1, bf16* ph, bf16* pl) {
    bf16 h0 = __float2bfloat16(c0), h1 = __float2bfloat16(c1);
    __nv_bfloat162 vh; vh.x = h0; vh.y = h1;
    __nv_bfloat162 vl;
    vl.x = __float2bfloat16(c0 - __bfloat162float(h0));
    vl.y = __float2bfloat16(c1 - __bfloat162float(h1));
    *(__nv_bfloat162*)ph = vh;
    *(__nv_bfloat162*)pl = vl;
}

// ---------------- weight transpose-split (vectorized; z = layer) ----------------
__global__ __launch_bounds__(256)
void wsplit_kernel(const float* __restrict__ W, bf16* __restrict__ Th,
                   bf16* __restrict__ Tl, int K, int N) {
    __shared__ float tile[32][36];   // 144 B rows: float4-aligned
    size_t loff = (size_t)blockIdx.z * K * N;
    int nb = blockIdx.x * 32, kb = blockIdx.y * 32;
    int t = threadIdx.x;
    {
        int r = t >> 3, c4 = (t & 7) * 4;
        *(float4*)&tile[r][c4] =
            *(const float4*)(W + loff + (size_t)(kb + r) * N + nb + c4);
    }
    __syncthreads();
    {
        int wid = t >> 5, lane = t & 31;
        int col = wid*4 + (lane >> 3);
        int k4  = (lane & 7) * 4;
        float v0 = tile[k4+0][col];
        float v1 = tile[k4+1][col];
        float v2 = tile[k4+2][col];
        float v3 = tile[k4+3][col];
        bf16 h0 = __float2bfloat16(v0), h1 = __float2bfloat16(v1);
        bf16 h2 = __float2bfloat16(v2), h3 = __float2bfloat16(v3);
        __nv_bfloat162 ph0; ph0.x = h0; ph0.y = h1;
        __nv_bfloat162 ph1; ph1.x = h2; ph1.y = h3;
        __nv_bfloat162 pl0, pl1;
        pl0.x = __float2bfloat16(v0 - __bfloat162float(h0));
        pl0.y = __float2bfloat16(v1 - __bfloat162float(h1));
        pl1.x = __float2bfloat16(v2 - __bfloat162float(h2));
        pl1.y = __float2bfloat16(v3 - __bfloat162float(h3));
        size_t o = loff + (size_t)(nb + col) * K + kb + k4;
        *(__nv_bfloat162*)(Th + o)     = ph0;
        *(__nv_bfloat162*)(Th + o + 2) = ph1;
        *(__nv_bfloat162*)(Tl + o)     = pl0;
        *(__nv_bfloat162*)(Tl + o + 2) = pl1;
    }
}

// ---------------- mma.sync bf16-split GEMM + fused epilogue split ----------------
// Cf written only for cols >= cfmin (drops dead Q/K f32 writes in QKV gemm).
#define ROWB  80
#define TILEB (128*ROWB)
#define GEMM_SMEM (8*TILEB)
__global__ __launch_bounds__(256, 2)
void gemm_bf16_kernel(const bf16* __restrict__ Ah, const bf16* __restrict__ Al,
                      const bf16* __restrict__ Bh, const bf16* __restrict__ Bl,
                      const float* __restrict__ bias,
                      float* __restrict__ Cf, bf16* __restrict__ Ch, bf16* __restrict__ Cl,
                      int M, int N, int K, int relu, int cfmin)
{
    extern __shared__ char smem[];
    const uint32_t sb = smem_u32(smem);
    const int tid = threadIdx.x, lane = tid & 31, wid = tid >> 5;
    const int wm = (wid & 1) * 64, wn = (wid >> 1) * 32;
    const int m0 = blockIdx.y * 128, n0 = blockIdx.x * 128;

    const bf16* gsrc[4] = { Ah + (size_t)m0*K, Al + (size_t)m0*K,
                            Bh + (size_t)n0*K, Bl + (size_t)n0*K };

    const int lrow = tid >> 1;
    const int lc0  = (tid & 1) * 2;

    const int aMoff = ((lane >> 3) & 1) * 8 + (lane & 7);
    const int aKby  = (lane >> 4) * 16;
    const int bNoff4 = (lane >> 4) * 8 + (lane & 7);
    const int bKby4  = ((lane >> 3) & 1) * 16;

    const int nchunk = K >> 5;

    {
        uint32_t dst = sb;
#pragma unroll
        for (int v = 0; v < 4; v++) {
            const bf16* g = gsrc[v] + (size_t)lrow*K + lc0*8;
            uint32_t s = dst + v*TILEB + lrow*ROWB + lc0*16;
            cpasync16(s, g);
            cpasync16(s + 16, g + 8);
        }
        CP_COMMIT();
    }

    float acc[4][4][4];
#pragma unroll
    for (int a = 0; a < 4; a++)
#pragma unroll
        for (int b = 0; b < 4; b++)
#pragma unroll
            for (int c = 0; c < 4; c++) acc[a][b][c] = 0.f;

    for (int t = 0; t < nchunk; t++) {
        CP_WAIT0();
        __syncthreads();
        if (t + 1 < nchunk) {
            int k0 = (t + 1) * 32;
            uint32_t dst = sb + ((t + 1) & 1) * 4*TILEB;
#pragma unroll
            for (int v = 0; v < 4; v++) {
                const bf16* g = gsrc[v] + (size_t)lrow*K + k0 + lc0*8;
                uint32_t s = dst + v*TILEB + lrow*ROWB + lc0*16;
                cpasync16(s, g);
                cpasync16(s + 16, g + 8);
            }
            CP_COMMIT();
        }

        uint32_t base = sb + (t & 1) * 4*TILEB;
#pragma unroll
        for (int kk = 0; kk < 2; kk++) {
            uint32_t bh[4][2], bl[4][2];
#pragma unroll
            for (int np = 0; np < 2; np++) {
                uint32_t baddr = base + 2*TILEB + (wn + np*16 + bNoff4)*ROWB + kk*32 + bKby4;
                uint32_t r4[4];
                ldmx4(r4, baddr);
                bh[np*2][0] = r4[0]; bh[np*2][1] = r4[1];
                bh[np*2+1][0] = r4[2]; bh[np*2+1][1] = r4[3];
                ldmx4(r4, baddr + TILEB);
                bl[np*2][0] = r4[0]; bl[np*2][1] = r4[1];
                bl[np*2+1][0] = r4[2]; bl[np*2+1][1] = r4[3];
            }
#pragma unroll
            for (int mt = 0; mt < 4; mt++) {
                uint32_t ah[4], al[4];
                uint32_t aaddr = base + (wm + mt*16 + aMoff)*ROWB + kk*32 + aKby;
                ldmx4(ah, aaddr);
                ldmx4(al, aaddr + TILEB);
#pragma unroll
                for (int nt = 0; nt < 4; nt++) {
                    mma16816(acc[mt][nt], ah, bh[nt]);
                    mma16816(acc[mt][nt], al, bh[nt]);
                    mma16816(acc[mt][nt], ah, bl[nt]);
                }
            }
        }
    }

    const int r0 = lane >> 2, cq = (lane & 3) * 2;
#pragma unroll
    for (int mt = 0; mt < 4; mt++) {
#pragma unroll
        for (int nt = 0; nt < 4; nt++) {
            int row = m0 + wm + mt*16 + r0;
            int col = n0 + wn + nt*8 + cq;
            float b0 = bias[col], b1 = bias[col + 1];
            float c0 = acc[mt][nt][0] + b0, c1 = acc[mt][nt][1] + b1;
            float c2 = acc[mt][nt][2] + b0, c3 = acc[mt][nt][3] + b1;
            if (relu) {
                c0 = fmaxf(c0, 0.f); c1 = fmaxf(c1, 0.f);
                c2 = fmaxf(c2, 0.f); c3 = fmaxf(c3, 0.f);
            }
            size_t o0 = (size_t)row*N + col, o1 = (size_t)(row + 8)*N + col;
            if (Cf && col >= cfmin) {
                *(float2*)&Cf[o0] = make_float2(c0, c1);
                *(float2*)&Cf[o1] = make_float2(c2, c3);
            }
            if (Ch) {
                split2(c0, c1, Ch + o0, Cl + o0);
                split2(c2, c3, Ch + o1, Cl + o1);
            }
        }
    }
}

// ---------------- positional encoding add (+ split) ----------------
__global__ void pos_add_kernel(const float* __restrict__ x, float* __restrict__ out,
                               bf16* __restrict__ oh, bf16* __restrict__ ol) {
    int row = blockIdx.x;
    int s = row & (SEQ - 1);
    const float c = -logf(10000.0f) / (float)DM;
    for (int d = threadIdx.x; d < DM; d += blockDim.x) {
        int i2 = d & ~1;
        float ang = (float)s * expf((float)i2 * c);
        float pe = (d & 1) ? cosf(ang) : sinf(ang);
        float v = x[(size_t)row*DM + d] + pe;
        out[(size_t)row*DM + d] = v;
        bf16 hv = __float2bfloat16(v);
        oh[(size_t)row*DM + d] = hv;
        ol[(size_t)row*DM + d] = __float2bfloat16(v - __bfloat162float(hv));
    }
}

// ---------------- attention: TC scores + SIMT softmax/PV (R11 config) ----------
#define P_LD   1032
#define QPITCH 72
#define SM_P   0
#define SM_QH  (32*P_LD*4)
#define SM_QL  (SM_QH + 32*QPITCH*2)
#define SM_KH  (SM_QL + 32*QPITCH*2)
#define SM_KL  (SM_KH + 128*QPITCH*2)
#define SM_V   SM_KH
#define ATT_SMEM (SM_KL + 128*QPITCH*2)          // 178176 B
__global__ __launch_bounds__(256)
void attn_kernel(const float* __restrict__ qkv,
                 const bf16* __restrict__ qkh, const bf16* __restrict__ qkl,
                 bf16* __restrict__ ctxh, bf16* __restrict__ ctxl)
{
    extern __shared__ char smraw[];
    float* P = (float*)(smraw + SM_P);
    const uint32_t sb = smem_u32(smraw);

    const int tid = threadIdx.x, lane = tid & 31, wid = tid >> 5;
    const int q0  = blockIdx.x * 32;
    const int h   = blockIdx.y;
    const int b   = blockIdx.z;
    const size_t rowbase = (size_t)b*SEQ;
    const int    colQ = h*HD, colK = DM + h*HD, colV = 2*DM + h*HD;

    {
        int r = tid >> 3, v = tid & 7;
        *(uint4*)(smraw + SM_QH + (r*QPITCH + v*8)*2) =
            *(const uint4*)(qkh + (rowbase + q0 + r)*QKVD + colQ + v*8);
        *(uint4*)(smraw + SM_QL + (r*QPITCH + v*8)*2) =
            *(const uint4*)(qkl + (rowbase + q0 + r)*QKVD + colQ + v*8);
    }

    const int aMoff = ((lane >> 3) & 1) * 8 + (lane & 7);
    const int aKby  = (lane >> 4) * 16;
    const int bNoff = lane & 7;
    const int bKby  = ((lane >> 3) & 1) * 16;
    const int nbase = wid * 16;
    const float scale = 0.125f;

    for (int kt = 0; kt < 8; kt++) {
#pragma unroll
        for (int i = 0; i < 4; i++) {
            int idx = tid + i*256;
            int r = idx >> 3, v = idx & 7;
            *(uint4*)(smraw + SM_KH + (r*QPITCH + v*8)*2) =
                *(const uint4*)(qkh + (rowbase + kt*128 + r)*QKVD + colK + v*8);
            *(uint4*)(smraw + SM_KL + (r*QPITCH + v*8)*2) =
                *(const uint4*)(qkl + (rowbase + kt*128 + r)*QKVD + colK + v*8);
        }
        __syncthreads();

        float acc[2][2][4];
#pragma unroll
        for (int i = 0; i < 2; i++)
#pragma unroll
            for (int j = 0; j < 2; j++)
#pragma unroll
                for (int c = 0; c < 4; c++) acc[i][j][c] = 0.f;

#pragma unroll
        for (int kk = 0; kk < 4; kk++) {
            uint32_t ah[2][4], al[2][4], bh[2][2], bl[2][2];
#pragma unroll
            for (int mt = 0; mt < 2; mt++) {
                uint32_t aaddr = sb + SM_QH + (mt*16 + aMoff)*QPITCH*2 + kk*32 + aKby;
                ldmx4(ah[mt], aaddr);
                ldmx4(al[mt], aaddr + (SM_QL - SM_QH));
            }
#pragma unroll
            for (int nt = 0; nt < 2; nt++) {
                uint32_t baddr = sb + SM_KH + (nbase + nt*8 + bNoff)*QPITCH*2 + kk*32 + bKby;
                ldmx2(bh[nt], baddr);
                ldmx2(bl[nt], baddr + (SM_KL - SM_KH));
            }
#pragma unroll
            for (int mt = 0; mt < 2; mt++)
#pragma unroll
                for (int nt = 0; nt < 2; nt++) {
                    mma16816(acc[mt][nt], ah[mt], bh[nt]);
                    mma16816(acc[mt][nt], al[mt], bh[nt]);
                    mma16816(acc[mt][nt], ah[mt], bl[nt]);
                }
        }
        const int r0 = lane >> 2, cq = (lane & 3) * 2;
#pragma unroll
        for (int mt = 0; mt < 2; mt++)
#pragma unroll
            for (int nt = 0; nt < 2; nt++) {
                int row = mt*16 + r0;
                int col = kt*128 + nbase + nt*8 + cq;
                P[row*P_LD + col]       = acc[mt][nt][0] * scale;
                P[row*P_LD + col + 1]   = acc[mt][nt][1] * scale;
                P[(row+8)*P_LD + col]   = acc[mt][nt][2] * scale;
                P[(row+8)*P_LD + col+1] = acc[mt][nt][3] * scale;
            }
        __syncthreads();
    }

    for (int r = wid; r < 32; r += 8) {
        float* row = P + r*P_LD;
        float m = -INFINITY;
        for (int t = lane; t < 1024; t += 32) m = fmaxf(m, row[t]);
#pragma unroll
        for (int o = 16; o; o >>= 1) m = fmaxf(m, __shfl_xor_sync(~0u, m, o));
        float s = 0.f;
        for (int t = lane; t < 1024; t += 32) { float e = __expf(row[t] - m); row[t] = e; s += e; }
#pragma unroll
        for (int o = 16; o; o >>= 1) s += __shfl_xor_sync(~0u, s, o);
        float inv = 1.f / s;
        for (int t = lane; t < 1024; t += 32)
            row[t] = fminf(fmaxf(row[t]*inv, 1e-6f), 1.f);
    }
    __syncthreads();

    float* Vs = (float*)(smraw + SM_V);
    const int txo = tid & 15;
    const int tyo = tid >> 4;
    u64 oacc[2][2] = { {0ull,0ull}, {0ull,0ull} };
    for (int vt = 0; vt < 8; vt++) {
        for (int f = tid; f < 128*16; f += 256) {
            int r = f >> 4, c4 = (f & 15) << 2;
            *(float4*)&Vs[r*64 + c4] =
                *(const float4*)(qkv + (rowbase + vt*128 + r)*QKVD + colV + c4);
        }
        __syncthreads();
#pragma unroll 4
        for (int k = 0; k < 128; k++) {
            u64 p0 = pack_dup(P[(tyo*2 + 0)*P_LD + vt*128 + k]);
            u64 p1 = pack_dup(P[(tyo*2 + 1)*P_LD + vt*128 + k]);
#pragma unroll
            for (int j = 0; j < 2; j++) {
                u64 v = *(const u64*)&Vs[k*64 + 2*(txo + 16*j)];
                oacc[0][j] = ffma2(p0, v, oacc[0][j]);
                oacc[1][j] = ffma2(p1, v, oacc[1][j]);
            }
        }
        __syncthreads();
    }
#pragma unroll
    for (int i = 0; i < 2; i++)
#pragma unroll
        for (int j = 0; j < 2; j++) {
            size_t o = (rowbase + q0 + tyo*2 + i)*DM + h*HD + 2*(txo + 16*j);
            split2(lo32(oacc[i][j]), hi32(oacc[i][j]), ctxh + o, ctxl + o);
        }
}

// ---------------- LayerNorm (+ optional split out) ----------------
__global__ __launch_bounds__(256)
void ln_kernel(const float* __restrict__ base, const float* __restrict__ delta,
               const float* __restrict__ g, const float* __restrict__ bta,
               float* __restrict__ out, bf16* __restrict__ oh, bf16* __restrict__ ol)
{
    __shared__ float rowv[DM];
    __shared__ float red[256];
    int row = blockIdx.x, tid = threadIdx.x;
    float local = 0.f;
    for (int d = tid; d < DM; d += 256) {
        float v = base[(size_t)row*DM + d];
        if (delta) v += delta[(size_t)row*DM + d];
        rowv[d] = v; local += v;
    }
    red[tid] = local; __syncthreads();
#pragma unroll
    for (int o = 128; o; o >>= 1) { if (tid < o) red[tid] += red[tid + o]; __syncthreads(); }
    float mean = red[0] * (1.0f/DM);
    __syncthreads();
    local = 0.f;
    for (int d = tid; d < DM; d += 256) { float dv = rowv[d] - mean; local += dv*dv; }
    red[tid] = local; __syncthreads();
#pragma unroll
    for (int o = 128; o; o >>= 1) { if (tid < o) red[tid] += red[tid + o]; __syncthreads(); }
    float inv = rsqrtf(red[0] * (1.0f/DM) + 1e-5f);
    for (int d = tid; d < DM; d += 256) {
        float v = (rowv[d] - mean)*inv*g[d] + bta[d];
        out[(size_t)row*DM + d] = v;
        if (oh) {
            bf16 hv = __float2bfloat16(v);
            oh[(size_t)row*DM + d] = hv;
            ol[(size_t)row*DM + d] = __float2bfloat16(v - __bfloat162float(hv));
        }
    }
}

// ---------------- orchestration ----------------
extern "C" void kernel_launch(void* const* d_in, const int* in_sizes, int n_in,
                              void* d_out, int out_size)
{
    const float* x    = (const float*)d_in[0];
    const float* Wqkv = (const float*)d_in[1];
    const float* bqkv = (const float*)d_in[2];
    const float* Wo   = (const float*)d_in[3];
    const float* bo   = (const float*)d_in[4];
    const float* ln1g = (const float*)d_in[5];
    const float* ln1b = (const float*)d_in[6];
    const float* W1   = (const float*)d_in[7];
    const float* b1   = (const float*)d_in[8];
    const float* W2   = (const float*)d_in[9];
    const float* b2   = (const float*)d_in[10];
    const float* ln2g = (const float*)d_in[11];
    const float* ln2b = (const float*)d_in[12];
    const float* lnfg = (const float*)d_in[13];
    const float* lnfb = (const float*)d_in[14];
    float* out = (float*)d_out;

    float *h, *qkv, *mid;
    bf16 *hh, *hl, *qh, *ql, *ch, *cl, *mh, *ml;
    bf16 *wqkvTh, *wqkvTl, *woTh, *woTl, *w1Th, *w1Tl, *w2Th, *w2Tl;
    cudaGetSymbolAddress((void**)&h,   g_h);
    cudaGetSymbolAddress((void**)&qkv, g_qkv);
    cudaGetSymbolAddress((void**)&mid, g_mid);
    cudaGetSymbolAddress((void**)&hh,  g_hh);
    cudaGetSymbolAddress((void**)&hl,  g_hl);
    cudaGetSymbolAddress((void**)&qh,  g_qh);
    cudaGetSymbolAddress((void**)&ql,  g_ql);
    cudaGetSymbolAddress((void**)&ch,  g_ch);
    cudaGetSymbolAddress((void**)&cl,  g_cl);
    cudaGetSymbolAddress((void**)&mh,  g_mh);
    cudaGetSymbolAddress((void**)&ml,  g_ml);
    cudaGetSymbolAddress((void**)&wqkvTh, g_wqkvT_h);
    cudaGetSymbolAddress((void**)&wqkvTl, g_wqkvT_l);
    cudaGetSymbolAddress((void**)&woTh, g_woT_h);
    cudaGetSymbolAddress((void**)&woTl, g_woT_l);
    cudaGetSymbolAddress((void**)&w1Th, g_w1T_h);
    cudaGetSymbolAddress((void**)&w1Tl, g_w1T_l);
    cudaGetSymbolAddress((void**)&w2Th, g_w2T_h);
    cudaGetSymbolAddress((void**)&w2Tl, g_w2T_l);

    cudaFuncSetAttribute(attn_kernel, cudaFuncAttributeMaxDynamicSharedMemorySize,
                         (int)ATT_SMEM);
    cudaFuncSetAttribute(gemm_bf16_kernel, cudaFuncAttributeMaxDynamicSharedMemorySize,
                         GEMM_SMEM);

    wsplit_kernel<<<dim3(QKVD/32, DM/32, NL), 256>>>(Wqkv, wqkvTh, wqkvTl, DM, QKVD);
    wsplit_kernel<<<dim3(DM/32,   DM/32, NL), 256>>>(Wo,   woTh,   woTl,   DM, DM);
    wsplit_kernel<<<dim3(FF/32,   DM/32, NL), 256>>>(W1,   w1Th,   w1Tl,   DM, FF);
    wsplit_kernel<<<dim3(DM/32,   FF/32, NL), 256>>>(W2,   w2Th,   w2Tl,   FF, DM);

    pos_add_kernel<<<MTOT, 256>>>(x, h, hh, hl);

    for (int l = 0; l < NL; l++) {
        // qkv = h @ Wqkv + bqkv  (f32 only for the V third; splits for Q/K/V)
        gemm_bf16_kernel<<<dim3(QKVD/128, MTOT/128), 256, GEMM_SMEM>>>(
            hh, hl, wqkvTh + (size_t)l*QKVD*DM, wqkvTl + (size_t)l*QKVD*DM,
            bqkv + (size_t)l*QKVD, qkv, qh, ql, MTOT, QKVD, DM, 0, 2*DM);
        // attention -> ctx splits
        attn_kernel<<<dim3(SEQ/32, NH, BATCH), 256, ATT_SMEM>>>(qkv, qh, ql, ch, cl);
        // proj = ctx @ Wo + bo (f32 only)
        gemm_bf16_kernel<<<dim3(DM/128, MTOT/128), 256, GEMM_SMEM>>>(
            ch, cl, woTh + (size_t)l*DM*DM, woTl + (size_t)l*DM*DM,
            bo + (size_t)l*DM, mid, nullptr, nullptr, MTOT, DM, DM, 0, 0);
        ln_kernel<<<MTOT, 256>>>(h, mid, ln1g + (size_t)l*DM, ln1b + (size_t)l*DM, h, hh, hl);
        // mid = relu(h @ W1 + b1)  (splits only)
        gemm_bf16_kernel<<<dim3(FF/128, MTOT/128), 256, GEMM_SMEM>>>(
            hh, hl, w1Th + (size_t)l*FF*DM, w1Tl + (size_t)l*FF*DM,
            b1 + (size_t)l*FF, nullptr, mh, ml, MTOT, FF, DM, 1, 0);
        // ffn = mid @ W2 + b2 (f32 only)
        gemm_bf16_kernel<<<dim3(DM/128, MTOT/128), 256, GEMM_SMEM>>>(
            mh, ml, w2Th + (size_t)l*DM*FF, w2Tl + (size_t)l*DM*FF,
            b2 + (size_t)l*DM, mid, nullptr, nullptr, MTOT, DM, FF, 0, 0);
        ln_kernel<<<MTOT, 256>>>(h, mid, ln2g + (size_t)l*DM, ln2b + (size_t)l*DM, h, hh, hl);
    }

    ln_kernel<<<MTOT, 256>>>(h, nullptr, lnfg, lnfb, out, nullptr, nullptr);
}